// round 12
// baseline (speedup 1.0000x reference)
#include <cuda_runtime.h>
#include <math.h>

// Problem constants
#define HW    4096
#define WIDTH 64
#define BATCH 4

// Scratch (device globals — no allocation allowed in kernel_launch)
// g_qkv: pair-interleaved (B, 384, HW, 2): channel c of pixel p at
//        ((b*384 + (c>>1))*HW + p)*2 + (c&1).  q: groups 0..127,
//        k: 128..255, v: 256..383 (within each b).
static __device__ float g_qkv[(size_t)BATCH * 768 * HW];
static __device__ float g_att[(size_t)BATCH * 256 * HW];   // channel-major, tf32-rounded
static __device__ float g_xr[(size_t)BATCH * 256 * HW];    // tf32-rounded x
static __device__ float g_wqkv[768 * 256];                 // tf32-rounded qkv_w
static __device__ float g_wproj[256 * 256];                // tf32-rounded proj_w

// ---------------------------------------------------------------------------
__device__ __forceinline__ float tf32r(float x) {
    unsigned u;
    asm("cvt.rna.tf32.f32 %0, %1;" : "=r"(u) : "f"(x));
    return __uint_as_float(u);
}

// One launch rounds all three GEMM inputs (x, qkv_w, proj_w) to tf32.
#define NX4   (BATCH * 256 * HW / 4)
#define NW1_4 (768 * 256 / 4)
#define NW2_4 (256 * 256 / 4)
__global__ void round_all_tf32(const float* __restrict__ x,
                               const float* __restrict__ w1,
                               const float* __restrict__ w2,
                               float* __restrict__ xo,
                               float* __restrict__ w1o,
                               float* __restrict__ w2o)
{
    int i = blockIdx.x * blockDim.x + threadIdx.x;
    const float4* in; float4* out; int idx;
    if (i < NX4)                { in = (const float4*)x;  out = (float4*)xo;  idx = i; }
    else if (i < NX4 + NW1_4)   { in = (const float4*)w1; out = (float4*)w1o; idx = i - NX4; }
    else if (i < NX4 + NW1_4 + NW2_4) { in = (const float4*)w2; out = (float4*)w2o; idx = i - NX4 - NW1_4; }
    else return;
    float4 v = in[idx];
    out[idx] = make_float4(tf32r(v.x), tf32r(v.y), tf32r(v.z), tf32r(v.w));
}

__device__ __forceinline__ void mma_tf32(float c[4], const unsigned a[4], const unsigned b[2]) {
    asm volatile(
        "mma.sync.aligned.m16n8k8.row.col.f32.tf32.tf32.f32 "
        "{%0,%1,%2,%3}, {%4,%5,%6,%7}, {%8,%9}, {%0,%1,%2,%3};\n"
        : "+f"(c[0]), "+f"(c[1]), "+f"(c[2]), "+f"(c[3])
        : "r"(a[0]), "r"(a[1]), "r"(a[2]), "r"(a[3]), "r"(b[0]), "r"(b[1]));
}

__device__ __forceinline__ void ldsm_x4(unsigned r[4], const float* p) {
    unsigned addr = (unsigned)__cvta_generic_to_shared(p);
    asm volatile(
        "ldmatrix.sync.aligned.m8n8.x4.shared.b16 {%0,%1,%2,%3}, [%4];"
        : "=r"(r[0]), "=r"(r[1]), "=r"(r[2]), "=r"(r[3]) : "r"(addr));
}

__device__ __forceinline__ void cp_async16(void* smem, const void* gmem) {
    unsigned s = (unsigned)__cvta_generic_to_shared(smem);
    asm volatile("cp.async.cg.shared.global [%0], [%1], 16;" :: "r"(s), "l"(gmem));
}
#define CP_COMMIT() asm volatile("cp.async.commit_group;")
#define CP_WAIT0()  asm volatile("cp.async.wait_group 0;" ::: "memory")
#define CP_WAIT1()  asm volatile("cp.async.wait_group 1;" ::: "memory")

// ---------------------------------------------------------------------------
// TF32 tensor-core GEMM with bias, 3-stage cp.async pipeline (R11 winner).
// ilv=1: store C pair-interleaved ((m,n) -> C[(m>>1)*2N + n*2 + (m&1)]).
// ---------------------------------------------------------------------------
#define BK   32
#define PADK 36
#define PADN 136
#define AS_STAGE (128 * PADK)
#define BS_STAGE (BK * PADN)
#define SMEM_FLOATS (3 * AS_STAGE + 3 * BS_STAGE)
#define SMEM_BYTES  (SMEM_FLOATS * 4)

__global__ void __launch_bounds__(256, 2) gemm_tf32_bias(
    const float* __restrict__ W, const float* __restrict__ X,
    const float* __restrict__ bias, float* __restrict__ C,
    int M, int N, int K, int ilv)
{
    extern __shared__ float smem[];
    float* const Abase = smem;
    float* const Bbase = smem + 3 * AS_STAGE;

    const int b  = blockIdx.z;
    const float* Xb = X + (size_t)b * K * N;
    float*       Cb = C + (size_t)b * M * N;
    const int m0 = blockIdx.y * 128;
    const int n0 = blockIdx.x * 128;
    const int tid  = threadIdx.x;
    const int lane = tid & 31;
    const int warp = tid >> 5;
    const int wm = (warp >> 2) * 64;
    const int wn = (warp & 3) * 32;
    const int g  = lane >> 2;
    const int t  = lane & 3;

    const int row_a = lane & 15;
    const int col_a = (lane >> 4) * 4;

    const int ar = tid & 127;
    const int akb = (tid >> 7) * 16;
    const int br = tid >> 5;
    const int bc = (tid & 31) * 4;

    const float* gA = &W[(size_t)(m0 + ar) * K + akb];
    const float* gB = &Xb[(size_t)br * N + n0 + bc];

    float acc[4][4][4];
#pragma unroll
    for (int i = 0; i < 4; ++i)
#pragma unroll
        for (int j = 0; j < 4; ++j)
#pragma unroll
            for (int r = 0; r < 4; ++r) acc[i][j][r] = 0.f;

    // Prologue: stages 0 and 1 in flight
#pragma unroll
    for (int st = 0; st < 2; ++st) {
        float* sA = Abase + st * AS_STAGE + ar * PADK + akb;
        float* sB = Bbase + st * BS_STAGE + br * PADN + bc;
        const int ko = st * BK;
#pragma unroll
        for (int i = 0; i < 4; ++i)
            cp_async16(sA + i * 4, gA + ko + i * 4);
#pragma unroll
        for (int j = 0; j < 4; ++j)
            cp_async16(sB + j * 8 * PADN, gB + (size_t)(ko + j * 8) * N);
        CP_COMMIT();
    }
    CP_WAIT1();
    __syncthreads();

    int cur = 0;
    for (int k0 = 0; k0 < K; k0 += BK) {
        const float* As = Abase + cur * AS_STAGE;
        const float* Bs = Bbase + cur * BS_STAGE;
#pragma unroll
        for (int kk = 0; kk < BK; kk += 8) {
            unsigned af[4][4], bf[4][2];
#pragma unroll
            for (int mt = 0; mt < 4; ++mt)
                ldsm_x4(af[mt], As + (wm + mt * 16 + row_a) * PADK + kk + col_a);
#pragma unroll
            for (int nt = 0; nt < 4; ++nt) {
                const int nb = wn + nt * 8;
                bf[nt][0] = __float_as_uint(Bs[(kk + t    ) * PADN + nb + g]);
                bf[nt][1] = __float_as_uint(Bs[(kk + t + 4) * PADN + nb + g]);
            }
#pragma unroll
            for (int mt = 0; mt < 4; ++mt)
#pragma unroll
                for (int nt = 0; nt < 4; ++nt)
                    mma_tf32(acc[mt][nt], af[mt], bf[nt]);
        }

        if (k0 + BK < K) {
            const int k2 = k0 + 2 * BK;
            if (k2 < K) {
                const int st = (cur + 2) % 3;
                float* sA = Abase + st * AS_STAGE + ar * PADK + akb;
                float* sB = Bbase + st * BS_STAGE + br * PADN + bc;
#pragma unroll
                for (int i = 0; i < 4; ++i)
                    cp_async16(sA + i * 4, gA + k2 + i * 4);
#pragma unroll
                for (int j = 0; j < 4; ++j)
                    cp_async16(sB + j * 8 * PADN, gB + (size_t)(k2 + j * 8) * N);
                CP_COMMIT();
                CP_WAIT1();
            } else {
                CP_WAIT0();
            }
            __syncthreads();
            cur = (cur + 1) % 3;
        }
    }

    if (ilv == 0) {
#pragma unroll
        for (int mt = 0; mt < 4; ++mt) {
#pragma unroll
            for (int rh = 0; rh < 2; ++rh) {
                const int m = m0 + wm + mt * 16 + g + rh * 8;
                const float bv = bias[m];
#pragma unroll
                for (int nt = 0; nt < 4; ++nt) {
                    float2 o;
                    o.x = acc[mt][nt][rh * 2 + 0] + bv;
                    o.y = acc[mt][nt][rh * 2 + 1] + bv;
                    *(float2*)&Cb[(size_t)m * N + n0 + wn + nt * 8 + t * 2] = o;
                }
            }
        }
    } else {
        // Pair-interleave: (m,n) -> Cb[(m>>1)*2*N + n*2 + (m&1)]
#pragma unroll
        for (int mt = 0; mt < 4; ++mt) {
#pragma unroll
            for (int rh = 0; rh < 2; ++rh) {
                const int m = m0 + wm + mt * 16 + g + rh * 8;
                const float bv = bias[m];
                float* base = Cb + (size_t)(m >> 1) * 2 * N + (m & 1);
#pragma unroll
                for (int nt = 0; nt < 4; ++nt) {
                    const int n = n0 + wn + nt * 8 + t * 2;
                    base[(size_t)n * 2]       = acc[mt][nt][rh * 2 + 0] + bv;
                    base[(size_t)(n + 1) * 2] = acc[mt][nt][rh * 2 + 1] + bv;
                }
            }
        }
    }
}

// ---------------------------------------------------------------------------
// Fused multi-range neighborhood attention, pair-interleaved k/v (LDG.64).
// Per neighbor: 16+16 LDG.64 (vs 64 scalar) — 2x fewer load instructions,
// same L1 wavefront count, minimal live registers (float2 consumed inline).
// Output stays channel-major for the proj GEMM.
// ---------------------------------------------------------------------------
template<int KS, int DIL>
__device__ __forceinline__ void attend_range(
    const float2* __restrict__ qb, const float2* __restrict__ kb,
    const float2* __restrict__ vb, const float* __restrict__ s_erpb,
    float* __restrict__ ob, int x, int y)
{
    const int idx = y * WIDTH + x;

    float q[32];
#pragma unroll
    for (int gi = 0; gi < 16; ++gi) {
        float2 qv = qb[(size_t)gi * HW + idx];
        q[2 * gi + 0] = qv.x * 0.17677669529663687f;  // 32^-0.5
        q[2 * gi + 1] = qv.y * 0.17677669529663687f;
    }

    float s = 0.f;
    float acc[32];
#pragma unroll
    for (int d = 0; d < 32; ++d) acc[d] = 0.f;

#pragma unroll 1
    for (int i = 0; i < KS; ++i) {
        const int ny = y + (i - KS / 2) * DIL;
        const bool iby = ((unsigned)ny < (unsigned)WIDTH);
#pragma unroll 1
        for (int j = 0; j < KS; ++j) {
            const int nx = x + (j - KS / 2) * DIL;
            const float erpb = s_erpb[i * KS + j];
            if (iby && ((unsigned)nx < (unsigned)WIDTH)) {
                const int nidx = ny * WIDTH + nx;
                float d0 = 0.f, d1 = 0.f;
#pragma unroll
                for (int gi = 0; gi < 16; ++gi) {
                    float2 kv = kb[(size_t)gi * HW + nidx];
                    d0 += q[2 * gi + 0] * kv.x;
                    d1 += q[2 * gi + 1] * kv.y;
                }
                const float p = __expf(d0 + d1) * erpb;
                s += p;
#pragma unroll
                for (int gi = 0; gi < 16; ++gi) {
                    float2 vv = vb[(size_t)gi * HW + nidx];
                    acc[2 * gi + 0] += p * vv.x;
                    acc[2 * gi + 1] += p * vv.y;
                }
            } else {
                s += erpb;   // OOB: logit = rpb, v = 0
            }
        }
    }

    const float inv = 1.f / s;
#pragma unroll
    for (int d = 0; d < 32; ++d)
        ob[(size_t)d * HW + idx] = tf32r(acc[d] * inv);
}

__global__ void __launch_bounds__(256, 2) attn_fused(
    const float* __restrict__ qkv,
    const float* __restrict__ rpb0, const float* __restrict__ rpb1,
    const float* __restrict__ rpb2, float* __restrict__ att)
{
    __shared__ float s_erpb[81];

    const int bh = blockIdx.z;
    const int b  = bh >> 3;
    const int h  = bh & 7;
    const int tid = threadIdx.y * 32 + threadIdx.x;

    if (h < 4) {
        if (tid < 25) s_erpb[tid] = __expf(rpb0[h * 25 + tid]);
    } else if (h < 7) {
        if (tid < 49) s_erpb[tid] = __expf(rpb1[(h - 4) * 49 + tid]);
    } else {
        if (tid < 81) s_erpb[tid] = __expf(rpb2[tid]);
    }
    __syncthreads();

    const int x = blockIdx.x * 32 + threadIdx.x;
    const int y = blockIdx.y * 8 + threadIdx.y;

    // Pair-interleaved: q groups h*16.., k groups 128+h*16.., v groups 256+h*16..
    const float2* qb = (const float2*)qkv + ((size_t)b * 384 +       h * 16) * HW;
    const float2* kb = (const float2*)qkv + ((size_t)b * 384 + 128 + h * 16) * HW;
    const float2* vb = (const float2*)qkv + ((size_t)b * 384 + 256 + h * 16) * HW;
    float* ob = att + ((size_t)b * 256 + h * 32) * HW;

    if (h < 4)       attend_range<5, 1>(qb, kb, vb, s_erpb, ob, x, y);
    else if (h < 7)  attend_range<7, 2>(qb, kb, vb, s_erpb, ob, x, y);
    else             attend_range<9, 3>(qb, kb, vb, s_erpb, ob, x, y);
}

// ---------------------------------------------------------------------------
extern "C" void kernel_launch(void* const* d_in, const int* in_sizes, int n_in,
                              void* d_out, int out_size)
{
    const float* x      = (const float*)d_in[0];
    const float* qkv_w  = (const float*)d_in[1];
    const float* qkv_b  = (const float*)d_in[2];
    const float* proj_w = (const float*)d_in[3];
    const float* proj_b = (const float*)d_in[4];
    const float* rpb0   = (const float*)d_in[5];
    const float* rpb1   = (const float*)d_in[6];
    const float* rpb2   = (const float*)d_in[7];
    float* out = (float*)d_out;

    float *qkv_ptr, *att_ptr, *xr_ptr, *wqkv_ptr, *wproj_ptr;
    cudaGetSymbolAddress((void**)&qkv_ptr,  g_qkv);
    cudaGetSymbolAddress((void**)&att_ptr,  g_att);
    cudaGetSymbolAddress((void**)&xr_ptr,   g_xr);
    cudaGetSymbolAddress((void**)&wqkv_ptr, g_wqkv);
    cudaGetSymbolAddress((void**)&wproj_ptr,g_wproj);

    static bool attr_set = false;
    if (!attr_set) {
        cudaFuncSetAttribute(gemm_tf32_bias,
                             cudaFuncAttributeMaxDynamicSharedMemorySize, SMEM_BYTES);
        attr_set = true;
    }

    // 0) Pre-round all GEMM inputs to tf32 in one launch
    {
        const int total = NX4 + NW1_4 + NW2_4;
        round_all_tf32<<<(total + 255) / 256, 256>>>(x, qkv_w, proj_w,
                                                     xr_ptr, wqkv_ptr, wproj_ptr);
    }

    // 1) QKV projection — TF32 tensor cores, pair-interleaved output
    gemm_tf32_bias<<<dim3(32, 6, BATCH), 256, SMEM_BYTES>>>(wqkv_ptr, xr_ptr, qkv_b, qkv_ptr, 768, HW, 256, 1);

    // 2) Fused multi-range neighborhood attention (float2 loads)
    attn_fused<<<dim3(2, 8, BATCH * 8), dim3(32, 8)>>>(qkv_ptr, rpb0, rpb1, rpb2, att_ptr);

    // 3) Output projection — TF32 tensor cores, standard output
    gemm_tf32_bias<<<dim3(32, 2, BATCH), 256, SMEM_BYTES>>>(wproj_ptr, att_ptr, proj_b, out, 256, HW, 256, 0);
}

// round 13
// speedup vs baseline: 1.0027x; 1.0027x over previous
#include <cuda_runtime.h>
#include <math.h>

// Problem constants
#define HW    4096
#define WIDTH 64
#define BATCH 4

// Scratch (device globals — no allocation allowed in kernel_launch)
static __device__ float g_qkv[(size_t)BATCH * 768 * HW];   // (B,768,HW) channel-major
static __device__ float g_att[(size_t)BATCH * 256 * HW];   // (B,256,HW), tf32-rounded at store
static __device__ float g_xr[(size_t)BATCH * 256 * HW];    // tf32-rounded x
static __device__ float g_wqkv[768 * 256];                 // tf32-rounded qkv_w
static __device__ float g_wproj[256 * 256];                // tf32-rounded proj_w

// ---------------------------------------------------------------------------
__device__ __forceinline__ float tf32r(float x) {
    unsigned u;
    asm("cvt.rna.tf32.f32 %0, %1;" : "=r"(u) : "f"(x));
    return __uint_as_float(u);
}

// One launch rounds all three GEMM inputs (x, qkv_w, proj_w) to tf32.
#define NX4   (BATCH * 256 * HW / 4)
#define NW1_4 (768 * 256 / 4)
#define NW2_4 (256 * 256 / 4)
__global__ void round_all_tf32(const float* __restrict__ x,
                               const float* __restrict__ w1,
                               const float* __restrict__ w2,
                               float* __restrict__ xo,
                               float* __restrict__ w1o,
                               float* __restrict__ w2o)
{
    int i = blockIdx.x * blockDim.x + threadIdx.x;
    const float4* in; float4* out; int idx;
    if (i < NX4)                { in = (const float4*)x;  out = (float4*)xo;  idx = i; }
    else if (i < NX4 + NW1_4)   { in = (const float4*)w1; out = (float4*)w1o; idx = i - NX4; }
    else if (i < NX4 + NW1_4 + NW2_4) { in = (const float4*)w2; out = (float4*)w2o; idx = i - NX4 - NW1_4; }
    else return;
    float4 v = in[idx];
    out[idx] = make_float4(tf32r(v.x), tf32r(v.y), tf32r(v.z), tf32r(v.w));
}

__device__ __forceinline__ void mma_tf32(float c[4], const unsigned a[4], const unsigned b[2]) {
    asm volatile(
        "mma.sync.aligned.m16n8k8.row.col.f32.tf32.tf32.f32 "
        "{%0,%1,%2,%3}, {%4,%5,%6,%7}, {%8,%9}, {%0,%1,%2,%3};\n"
        : "+f"(c[0]), "+f"(c[1]), "+f"(c[2]), "+f"(c[3])
        : "r"(a[0]), "r"(a[1]), "r"(a[2]), "r"(a[3]), "r"(b[0]), "r"(b[1]));
}

__device__ __forceinline__ void ldsm_x4(unsigned r[4], const float* p) {
    unsigned addr = (unsigned)__cvta_generic_to_shared(p);
    asm volatile(
        "ldmatrix.sync.aligned.m8n8.x4.shared.b16 {%0,%1,%2,%3}, [%4];"
        : "=r"(r[0]), "=r"(r[1]), "=r"(r[2]), "=r"(r[3]) : "r"(addr));
}

__device__ __forceinline__ void cp_async16(void* smem, const void* gmem) {
    unsigned s = (unsigned)__cvta_generic_to_shared(smem);
    asm volatile("cp.async.cg.shared.global [%0], [%1], 16;" :: "r"(s), "l"(gmem));
}
#define CP_COMMIT() asm volatile("cp.async.commit_group;")
#define CP_WAIT0()  asm volatile("cp.async.wait_group 0;" ::: "memory")
#define CP_WAIT1()  asm volatile("cp.async.wait_group 1;" ::: "memory")

// ---------------------------------------------------------------------------
// TF32 tensor-core GEMM with bias, 3-stage cp.async pipeline.
// Block 128x128x32, **16 warps (512 thr), warp tile 32x32** (2x4 m16n8k8).
// Half the registers per thread vs 8-warp version -> 32 warps/SM resident.
// A staged [m][k] PADK=36 (ldmatrix conflict-free); B staged [k][n] PADN=136.
// ---------------------------------------------------------------------------
#define BK   32
#define PADK 36
#define PADN 136
#define AS_STAGE (128 * PADK)
#define BS_STAGE (BK * PADN)
#define SMEM_FLOATS (3 * AS_STAGE + 3 * BS_STAGE)
#define SMEM_BYTES  (SMEM_FLOATS * 4)

__global__ void __launch_bounds__(512, 2) gemm_tf32_bias(
    const float* __restrict__ W, const float* __restrict__ X,
    const float* __restrict__ bias, float* __restrict__ C,
    int M, int N, int K)
{
    extern __shared__ float smem[];
    float* const Abase = smem;
    float* const Bbase = smem + 3 * AS_STAGE;

    const int b  = blockIdx.z;
    const float* Xb = X + (size_t)b * K * N;
    float*       Cb = C + (size_t)b * M * N;
    const int m0 = blockIdx.y * 128;
    const int n0 = blockIdx.x * 128;
    const int tid  = threadIdx.x;
    const int lane = tid & 31;
    const int warp = tid >> 5;                 // 0..15
    const int wm = (warp >> 2) * 32;           // 0/32/64/96
    const int wn = (warp & 3) * 32;            // 0/32/64/96
    const int g  = lane >> 2;
    const int t  = lane & 3;

    const int row_a = lane & 15;
    const int col_a = (lane >> 4) * 4;

    // Global-load mapping (512 threads)
    const int ar  = tid & 127;                 // A row; k chunk base:
    const int akb = (tid >> 7) * 8;            //   0/8/16/24, two cp16 at +0,+4
    const int br  = tid >> 4;                  // B k row 0..31
    const int bcb = (tid & 15) * 8;            // B n col, two cp16 at +0,+4

    const float* gA = &W[(size_t)(m0 + ar) * K + akb];
    const float* gB = &Xb[(size_t)br * N + n0 + bcb];

    float acc[2][4][4];
#pragma unroll
    for (int i = 0; i < 2; ++i)
#pragma unroll
        for (int j = 0; j < 4; ++j)
#pragma unroll
            for (int r = 0; r < 4; ++r) acc[i][j][r] = 0.f;

    // Prologue: stages 0 and 1 in flight
#pragma unroll
    for (int st = 0; st < 2; ++st) {
        float* sA = Abase + st * AS_STAGE + ar * PADK + akb;
        float* sB = Bbase + st * BS_STAGE + br * PADN + bcb;
        const int ko = st * BK;
        cp_async16(sA,     gA + ko);
        cp_async16(sA + 4, gA + ko + 4);
        cp_async16(sB,     gB + (size_t)ko * N);
        cp_async16(sB + 4, gB + (size_t)ko * N + 4);
        CP_COMMIT();
    }
    CP_WAIT1();
    __syncthreads();

    int cur = 0;
    for (int k0 = 0; k0 < K; k0 += BK) {
        const float* As = Abase + cur * AS_STAGE;
        const float* Bs = Bbase + cur * BS_STAGE;
#pragma unroll
        for (int kk = 0; kk < BK; kk += 8) {
            unsigned af[2][4], bf[4][2];
#pragma unroll
            for (int mt = 0; mt < 2; ++mt)
                ldsm_x4(af[mt], As + (wm + mt * 16 + row_a) * PADK + kk + col_a);
#pragma unroll
            for (int nt = 0; nt < 4; ++nt) {
                const int nb = wn + nt * 8;
                bf[nt][0] = __float_as_uint(Bs[(kk + t    ) * PADN + nb + g]);
                bf[nt][1] = __float_as_uint(Bs[(kk + t + 4) * PADN + nb + g]);
            }
#pragma unroll
            for (int mt = 0; mt < 2; ++mt)
#pragma unroll
                for (int nt = 0; nt < 4; ++nt)
                    mma_tf32(acc[mt][nt], af[mt], bf[nt]);
        }

        if (k0 + BK < K) {
            const int k2 = k0 + 2 * BK;
            if (k2 < K) {
                const int st = (cur + 2) % 3;
                float* sA = Abase + st * AS_STAGE + ar * PADK + akb;
                float* sB = Bbase + st * BS_STAGE + br * PADN + bcb;
                cp_async16(sA,     gA + k2);
                cp_async16(sA + 4, gA + k2 + 4);
                cp_async16(sB,     gB + (size_t)k2 * N);
                cp_async16(sB + 4, gB + (size_t)k2 * N + 4);
                CP_COMMIT();
                CP_WAIT1();
            } else {
                CP_WAIT0();
            }
            __syncthreads();
            cur = (cur + 1) % 3;
        }
    }

    // Epilogue: c0,c1 = row g, cols 2t,2t+1; c2,c3 = row g+8
#pragma unroll
    for (int mt = 0; mt < 2; ++mt) {
#pragma unroll
        for (int rh = 0; rh < 2; ++rh) {
            const int m = m0 + wm + mt * 16 + g + rh * 8;
            const float bv = bias[m];
#pragma unroll
            for (int nt = 0; nt < 4; ++nt) {
                float2 o;
                o.x = acc[mt][nt][rh * 2 + 0] + bv;
                o.y = acc[mt][nt][rh * 2 + 1] + bv;
                *(float2*)&Cb[(size_t)m * N + n0 + wn + nt * 8 + t * 2] = o;
            }
        }
    }
}

// ---------------------------------------------------------------------------
// Fused multi-range neighborhood attention (R11 winner, reverted verbatim).
// ---------------------------------------------------------------------------
template<int KS, int DIL>
__device__ __forceinline__ void attend_range(
    const float* __restrict__ qb, const float* __restrict__ kb,
    const float* __restrict__ vb, const float* __restrict__ s_erpb,
    float* __restrict__ ob, int x, int y)
{
    const int idx = y * WIDTH + x;

    float q[32];
#pragma unroll
    for (int d = 0; d < 32; ++d)
        q[d] = qb[(size_t)d * HW + idx] * 0.17677669529663687f;  // 32^-0.5

    float s = 0.f;
    float acc[32];
#pragma unroll
    for (int d = 0; d < 32; ++d) acc[d] = 0.f;

#pragma unroll 1
    for (int i = 0; i < KS; ++i) {
        const int ny = y + (i - KS / 2) * DIL;
        const bool iby = ((unsigned)ny < (unsigned)WIDTH);
#pragma unroll 1
        for (int j = 0; j < KS; ++j) {
            const int nx = x + (j - KS / 2) * DIL;
            const float erpb = s_erpb[i * KS + j];
            if (iby && ((unsigned)nx < (unsigned)WIDTH)) {
                const int nidx = ny * WIDTH + nx;
                float dot = 0.f;
#pragma unroll
                for (int d = 0; d < 32; ++d)
                    dot += q[d] * kb[(size_t)d * HW + nidx];
                const float p = __expf(dot) * erpb;
                s += p;
#pragma unroll
                for (int d = 0; d < 32; ++d)
                    acc[d] += p * vb[(size_t)d * HW + nidx];
            } else {
                s += erpb;   // OOB: logit = rpb, v = 0
            }
        }
    }

    const float inv = 1.f / s;
#pragma unroll
    for (int d = 0; d < 32; ++d)
        ob[(size_t)d * HW + idx] = tf32r(acc[d] * inv);
}

__global__ void __launch_bounds__(256, 2) attn_fused(
    const float* __restrict__ qkv,
    const float* __restrict__ rpb0, const float* __restrict__ rpb1,
    const float* __restrict__ rpb2, float* __restrict__ att)
{
    __shared__ float s_erpb[81];

    const int bh = blockIdx.z;
    const int b  = bh >> 3;
    const int h  = bh & 7;
    const int tid = threadIdx.y * 32 + threadIdx.x;

    if (h < 4) {
        if (tid < 25) s_erpb[tid] = __expf(rpb0[h * 25 + tid]);
    } else if (h < 7) {
        if (tid < 49) s_erpb[tid] = __expf(rpb1[(h - 4) * 49 + tid]);
    } else {
        if (tid < 81) s_erpb[tid] = __expf(rpb2[tid]);
    }
    __syncthreads();

    const int x = blockIdx.x * 32 + threadIdx.x;
    const int y = blockIdx.y * 8 + threadIdx.y;

    const float* qb = qkv + ((size_t)b * 768 + h * 32) * HW;
    const float* kb = qb + (size_t)256 * HW;
    const float* vb = qb + (size_t)512 * HW;
    float* ob = att + ((size_t)b * 256 + h * 32) * HW;

    if (h < 4)       attend_range<5, 1>(qb, kb, vb, s_erpb, ob, x, y);
    else if (h < 7)  attend_range<7, 2>(qb, kb, vb, s_erpb, ob, x, y);
    else             attend_range<9, 3>(qb, kb, vb, s_erpb, ob, x, y);
}

// ---------------------------------------------------------------------------
extern "C" void kernel_launch(void* const* d_in, const int* in_sizes, int n_in,
                              void* d_out, int out_size)
{
    const float* x      = (const float*)d_in[0];
    const float* qkv_w  = (const float*)d_in[1];
    const float* qkv_b  = (const float*)d_in[2];
    const float* proj_w = (const float*)d_in[3];
    const float* proj_b = (const float*)d_in[4];
    const float* rpb0   = (const float*)d_in[5];
    const float* rpb1   = (const float*)d_in[6];
    const float* rpb2   = (const float*)d_in[7];
    float* out = (float*)d_out;

    float *qkv_ptr, *att_ptr, *xr_ptr, *wqkv_ptr, *wproj_ptr;
    cudaGetSymbolAddress((void**)&qkv_ptr,  g_qkv);
    cudaGetSymbolAddress((void**)&att_ptr,  g_att);
    cudaGetSymbolAddress((void**)&xr_ptr,   g_xr);
    cudaGetSymbolAddress((void**)&wqkv_ptr, g_wqkv);
    cudaGetSymbolAddress((void**)&wproj_ptr,g_wproj);

    static bool attr_set = false;
    if (!attr_set) {
        cudaFuncSetAttribute(gemm_tf32_bias,
                             cudaFuncAttributeMaxDynamicSharedMemorySize, SMEM_BYTES);
        attr_set = true;
    }

    // 0) Pre-round all GEMM inputs to tf32 in one launch
    {
        const int total = NX4 + NW1_4 + NW2_4;
        round_all_tf32<<<(total + 255) / 256, 256>>>(x, qkv_w, proj_w,
                                                     xr_ptr, wqkv_ptr, wproj_ptr);
    }

    // 1) QKV projection — TF32 tensor cores, 512-thread blocks
    gemm_tf32_bias<<<dim3(32, 6, BATCH), 512, SMEM_BYTES>>>(wqkv_ptr, xr_ptr, qkv_b, qkv_ptr, 768, HW, 256);

    // 2) Fused multi-range neighborhood attention (R11 winner)
    attn_fused<<<dim3(2, 8, BATCH * 8), dim3(32, 8)>>>(qkv_ptr, rpb0, rpb1, rpb2, att_ptr);

    // 3) Output projection — TF32 tensor cores, 512-thread blocks
    gemm_tf32_bias<<<dim3(32, 2, BATCH), 512, SMEM_BYTES>>>(wproj_ptr, att_ptr, proj_b, out, 256, HW, 256);
}

// round 14
// speedup vs baseline: 1.0999x; 1.0969x over previous
#include <cuda_runtime.h>
#include <math.h>

// Problem constants
#define HW    4096
#define WIDTH 64
#define BATCH 4

// Scratch (device globals — no allocation allowed in kernel_launch)
static __device__ float g_qkv[(size_t)BATCH * 768 * HW];   // (B,768,HW) channel-major
static __device__ float g_att[(size_t)BATCH * 256 * HW];   // (B,256,HW), tf32-rounded at store
static __device__ float g_xr[(size_t)BATCH * 256 * HW];    // tf32-rounded x
static __device__ float g_wqkv[768 * 256];                 // tf32-rounded qkv_w
static __device__ float g_wproj[256 * 256];                // tf32-rounded proj_w

// ---------------------------------------------------------------------------
__device__ __forceinline__ float tf32r(float x) {
    unsigned u;
    asm("cvt.rna.tf32.f32 %0, %1;" : "=r"(u) : "f"(x));
    return __uint_as_float(u);
}

// One launch rounds all three GEMM inputs (x, qkv_w, proj_w) to tf32.
#define NX4   (BATCH * 256 * HW / 4)
#define NW1_4 (768 * 256 / 4)
#define NW2_4 (256 * 256 / 4)
__global__ void round_all_tf32(const float* __restrict__ x,
                               const float* __restrict__ w1,
                               const float* __restrict__ w2,
                               float* __restrict__ xo,
                               float* __restrict__ w1o,
                               float* __restrict__ w2o)
{
    int i = blockIdx.x * blockDim.x + threadIdx.x;
    const float4* in; float4* out; int idx;
    if (i < NX4)                { in = (const float4*)x;  out = (float4*)xo;  idx = i; }
    else if (i < NX4 + NW1_4)   { in = (const float4*)w1; out = (float4*)w1o; idx = i - NX4; }
    else if (i < NX4 + NW1_4 + NW2_4) { in = (const float4*)w2; out = (float4*)w2o; idx = i - NX4 - NW1_4; }
    else return;
    float4 v = in[idx];
    out[idx] = make_float4(tf32r(v.x), tf32r(v.y), tf32r(v.z), tf32r(v.w));
}

__device__ __forceinline__ void mma_tf32(float c[4], const unsigned a[4], const unsigned b[2]) {
    asm volatile(
        "mma.sync.aligned.m16n8k8.row.col.f32.tf32.tf32.f32 "
        "{%0,%1,%2,%3}, {%4,%5,%6,%7}, {%8,%9}, {%0,%1,%2,%3};\n"
        : "+f"(c[0]), "+f"(c[1]), "+f"(c[2]), "+f"(c[3])
        : "r"(a[0]), "r"(a[1]), "r"(a[2]), "r"(a[3]), "r"(b[0]), "r"(b[1]));
}

__device__ __forceinline__ void ldsm_x4(unsigned r[4], const float* p) {
    unsigned addr = (unsigned)__cvta_generic_to_shared(p);
    asm volatile(
        "ldmatrix.sync.aligned.m8n8.x4.shared.b16 {%0,%1,%2,%3}, [%4];"
        : "=r"(r[0]), "=r"(r[1]), "=r"(r[2]), "=r"(r[3]) : "r"(addr));
}

__device__ __forceinline__ void cp_async16(void* smem, const void* gmem) {
    unsigned s = (unsigned)__cvta_generic_to_shared(smem);
    asm volatile("cp.async.cg.shared.global [%0], [%1], 16;" :: "r"(s), "l"(gmem));
}
#define CP_COMMIT() asm volatile("cp.async.commit_group;")
#define CP_WAIT0()  asm volatile("cp.async.wait_group 0;" ::: "memory")
#define CP_WAIT1()  asm volatile("cp.async.wait_group 1;" ::: "memory")

// ---------------------------------------------------------------------------
// TF32 tensor-core GEMM with bias, 3-stage cp.async pipeline (R11 winner).
// Block 128x128x32, 8 warps, warp tile 64x32 (4x4 m16n8k8 frags).
// A staged [m][k] PADK=36 (ldmatrix conflict-free); B staged [k][n] PADN=136.
// ---------------------------------------------------------------------------
#define BK   32
#define PADK 36
#define PADN 136
#define AS_STAGE (128 * PADK)
#define BS_STAGE (BK * PADN)
#define SMEM_FLOATS (3 * AS_STAGE + 3 * BS_STAGE)
#define SMEM_BYTES  (SMEM_FLOATS * 4)

__global__ void __launch_bounds__(256, 2) gemm_tf32_bias(
    const float* __restrict__ W, const float* __restrict__ X,
    const float* __restrict__ bias, float* __restrict__ C,
    int M, int N, int K)
{
    extern __shared__ float smem[];
    float* const Abase = smem;
    float* const Bbase = smem + 3 * AS_STAGE;

    const int b  = blockIdx.z;
    const float* Xb = X + (size_t)b * K * N;
    float*       Cb = C + (size_t)b * M * N;
    const int m0 = blockIdx.y * 128;
    const int n0 = blockIdx.x * 128;
    const int tid  = threadIdx.x;
    const int lane = tid & 31;
    const int warp = tid >> 5;
    const int wm = (warp >> 2) * 64;
    const int wn = (warp & 3) * 32;
    const int g  = lane >> 2;
    const int t  = lane & 3;

    const int row_a = lane & 15;
    const int col_a = (lane >> 4) * 4;

    const int ar = tid & 127;
    const int akb = (tid >> 7) * 16;
    const int br = tid >> 5;
    const int bc = (tid & 31) * 4;

    const float* gA = &W[(size_t)(m0 + ar) * K + akb];
    const float* gB = &Xb[(size_t)br * N + n0 + bc];

    float acc[4][4][4];
#pragma unroll
    for (int i = 0; i < 4; ++i)
#pragma unroll
        for (int j = 0; j < 4; ++j)
#pragma unroll
            for (int r = 0; r < 4; ++r) acc[i][j][r] = 0.f;

    // Prologue: stages 0 and 1 in flight
#pragma unroll
    for (int st = 0; st < 2; ++st) {
        float* sA = Abase + st * AS_STAGE + ar * PADK + akb;
        float* sB = Bbase + st * BS_STAGE + br * PADN + bc;
        const int ko = st * BK;
#pragma unroll
        for (int i = 0; i < 4; ++i)
            cp_async16(sA + i * 4, gA + ko + i * 4);
#pragma unroll
        for (int j = 0; j < 4; ++j)
            cp_async16(sB + j * 8 * PADN, gB + (size_t)(ko + j * 8) * N);
        CP_COMMIT();
    }
    CP_WAIT1();
    __syncthreads();

    int cur = 0;
    for (int k0 = 0; k0 < K; k0 += BK) {
        const float* As = Abase + cur * AS_STAGE;
        const float* Bs = Bbase + cur * BS_STAGE;
#pragma unroll
        for (int kk = 0; kk < BK; kk += 8) {
            unsigned af[4][4], bf[4][2];
#pragma unroll
            for (int mt = 0; mt < 4; ++mt)
                ldsm_x4(af[mt], As + (wm + mt * 16 + row_a) * PADK + kk + col_a);
#pragma unroll
            for (int nt = 0; nt < 4; ++nt) {
                const int nb = wn + nt * 8;
                bf[nt][0] = __float_as_uint(Bs[(kk + t    ) * PADN + nb + g]);
                bf[nt][1] = __float_as_uint(Bs[(kk + t + 4) * PADN + nb + g]);
            }
#pragma unroll
            for (int mt = 0; mt < 4; ++mt)
#pragma unroll
                for (int nt = 0; nt < 4; ++nt)
                    mma_tf32(acc[mt][nt], af[mt], bf[nt]);
        }

        if (k0 + BK < K) {
            const int k2 = k0 + 2 * BK;
            if (k2 < K) {
                const int st = (cur + 2) % 3;
                float* sA = Abase + st * AS_STAGE + ar * PADK + akb;
                float* sB = Bbase + st * BS_STAGE + br * PADN + bc;
#pragma unroll
                for (int i = 0; i < 4; ++i)
                    cp_async16(sA + i * 4, gA + k2 + i * 4);
#pragma unroll
                for (int j = 0; j < 4; ++j)
                    cp_async16(sB + j * 8 * PADN, gB + (size_t)(k2 + j * 8) * N);
                CP_COMMIT();
                CP_WAIT1();
            } else {
                CP_WAIT0();
            }
            __syncthreads();
            cur = (cur + 1) % 3;
        }
    }

    // Epilogue: c0,c1 = row g, cols 2t,2t+1; c2,c3 = row g+8
#pragma unroll
    for (int mt = 0; mt < 4; ++mt) {
#pragma unroll
        for (int rh = 0; rh < 2; ++rh) {
            const int m = m0 + wm + mt * 16 + g + rh * 8;
            const float bv = bias[m];
#pragma unroll
            for (int nt = 0; nt < 4; ++nt) {
                float2 o;
                o.x = acc[mt][nt][rh * 2 + 0] + bv;
                o.y = acc[mt][nt][rh * 2 + 1] + bv;
                *(float2*)&Cb[(size_t)m * N + n0 + wn + nt * 8 + t * 2] = o;
            }
        }
    }
}

// ---------------------------------------------------------------------------
// Fused multi-range neighborhood attention (R11 winner), with heavy-first
// block ordering: z -> (b, h) permuted so KS=9 blocks are scheduled first,
// eliminating the straggler tail of the heaviest head group.
// ---------------------------------------------------------------------------
template<int KS, int DIL>
__device__ __forceinline__ void attend_range(
    const float* __restrict__ qb, const float* __restrict__ kb,
    const float* __restrict__ vb, const float* __restrict__ s_erpb,
    float* __restrict__ ob, int x, int y)
{
    const int idx = y * WIDTH + x;

    float q[32];
#pragma unroll
    for (int d = 0; d < 32; ++d)
        q[d] = qb[(size_t)d * HW + idx] * 0.17677669529663687f;  // 32^-0.5

    float s = 0.f;
    float acc[32];
#pragma unroll
    for (int d = 0; d < 32; ++d) acc[d] = 0.f;

#pragma unroll 1
    for (int i = 0; i < KS; ++i) {
        const int ny = y + (i - KS / 2) * DIL;
        const bool iby = ((unsigned)ny < (unsigned)WIDTH);
#pragma unroll 1
        for (int j = 0; j < KS; ++j) {
            const int nx = x + (j - KS / 2) * DIL;
            const float erpb = s_erpb[i * KS + j];
            if (iby && ((unsigned)nx < (unsigned)WIDTH)) {
                const int nidx = ny * WIDTH + nx;
                float dot = 0.f;
#pragma unroll
                for (int d = 0; d < 32; ++d)
                    dot += q[d] * kb[(size_t)d * HW + nidx];
                const float p = __expf(dot) * erpb;
                s += p;
#pragma unroll
                for (int d = 0; d < 32; ++d)
                    acc[d] += p * vb[(size_t)d * HW + nidx];
            } else {
                s += erpb;   // OOB: logit = rpb, v = 0
            }
        }
    }

    const float inv = 1.f / s;
#pragma unroll
    for (int d = 0; d < 32; ++d)
        ob[(size_t)d * HW + idx] = tf32r(acc[d] * inv);
}

__global__ void __launch_bounds__(256, 2) attn_fused(
    const float* __restrict__ qkv,
    const float* __restrict__ rpb0, const float* __restrict__ rpb1,
    const float* __restrict__ rpb2, float* __restrict__ att)
{
    __shared__ float s_erpb[81];

    // Heavy-first head order: KS=9 (h=7), then KS=7 (h=4..6), then KS=5 (h=0..3).
    const int ord = blockIdx.z & 7;
    const int b   = blockIdx.z >> 3;
    static const __device__ int h_order[8] = {7, 4, 5, 6, 0, 1, 2, 3};
    const int h = h_order[ord];

    const int tid = threadIdx.y * 32 + threadIdx.x;

    if (h < 4) {
        if (tid < 25) s_erpb[tid] = __expf(rpb0[h * 25 + tid]);
    } else if (h < 7) {
        if (tid < 49) s_erpb[tid] = __expf(rpb1[(h - 4) * 49 + tid]);
    } else {
        if (tid < 81) s_erpb[tid] = __expf(rpb2[tid]);
    }
    __syncthreads();

    const int x = blockIdx.x * 32 + threadIdx.x;
    const int y = blockIdx.y * 8 + threadIdx.y;

    const float* qb = qkv + ((size_t)b * 768 + h * 32) * HW;
    const float* kb = qb + (size_t)256 * HW;
    const float* vb = qb + (size_t)512 * HW;
    float* ob = att + ((size_t)b * 256 + h * 32) * HW;

    if (h < 4)       attend_range<5, 1>(qb, kb, vb, s_erpb, ob, x, y);
    else if (h < 7)  attend_range<7, 2>(qb, kb, vb, s_erpb, ob, x, y);
    else             attend_range<9, 3>(qb, kb, vb, s_erpb, ob, x, y);
}

// ---------------------------------------------------------------------------
extern "C" void kernel_launch(void* const* d_in, const int* in_sizes, int n_in,
                              void* d_out, int out_size)
{
    const float* x      = (const float*)d_in[0];
    const float* qkv_w  = (const float*)d_in[1];
    const float* qkv_b  = (const float*)d_in[2];
    const float* proj_w = (const float*)d_in[3];
    const float* proj_b = (const float*)d_in[4];
    const float* rpb0   = (const float*)d_in[5];
    const float* rpb1   = (const float*)d_in[6];
    const float* rpb2   = (const float*)d_in[7];
    float* out = (float*)d_out;

    float *qkv_ptr, *att_ptr, *xr_ptr, *wqkv_ptr, *wproj_ptr;
    cudaGetSymbolAddress((void**)&qkv_ptr,  g_qkv);
    cudaGetSymbolAddress((void**)&att_ptr,  g_att);
    cudaGetSymbolAddress((void**)&xr_ptr,   g_xr);
    cudaGetSymbolAddress((void**)&wqkv_ptr, g_wqkv);
    cudaGetSymbolAddress((void**)&wproj_ptr,g_wproj);

    static bool attr_set = false;
    if (!attr_set) {
        cudaFuncSetAttribute(gemm_tf32_bias,
                             cudaFuncAttributeMaxDynamicSharedMemorySize, SMEM_BYTES);
        attr_set = true;
    }

    // 0) Pre-round all GEMM inputs to tf32 in one launch
    {
        const int total = NX4 + NW1_4 + NW2_4;
        round_all_tf32<<<(total + 255) / 256, 256>>>(x, qkv_w, proj_w,
                                                     xr_ptr, wqkv_ptr, wproj_ptr);
    }

    // 1) QKV projection — TF32 tensor cores, 3-stage pipeline (R11)
    gemm_tf32_bias<<<dim3(32, 6, BATCH), 256, SMEM_BYTES>>>(wqkv_ptr, xr_ptr, qkv_b, qkv_ptr, 768, HW, 256);

    // 2) Fused multi-range neighborhood attention, heavy blocks first
    attn_fused<<<dim3(2, 8, BATCH * 8), dim3(32, 8)>>>(qkv_ptr, rpb0, rpb1, rpb2, att_ptr);

    // 3) Output projection — TF32 tensor cores, 3-stage pipeline (R11)
    gemm_tf32_bias<<<dim3(32, 2, BATCH), 256, SMEM_BYTES>>>(wproj_ptr, att_ptr, proj_b, out, 256, HW, 256);
}

// round 15
// speedup vs baseline: 1.1514x; 1.0469x over previous
#include <cuda_runtime.h>
#include <math.h>

// Problem constants
#define HW    4096
#define WIDTH 64
#define BATCH 4

// Scratch (device globals — no allocation allowed in kernel_launch)
static __device__ float g_qkv[(size_t)BATCH * 768 * HW];   // (B,768,HW) channel-major
static __device__ float g_att[(size_t)BATCH * 256 * HW];   // (B,256,HW), tf32-rounded at store
static __device__ float g_wqkv[768 * 256];                 // tf32-rounded qkv_w
static __device__ float g_wproj[256 * 256];                // tf32-rounded proj_w

// ---------------------------------------------------------------------------
__device__ __forceinline__ float tf32r(float x) {
    unsigned u;
    asm("cvt.rna.tf32.f32 %0, %1;" : "=r"(u) : "f"(x));
    return __uint_as_float(u);
}

// One launch rounds both weight matrices to tf32 (x stays raw: the MMA
// hardware truncates the B operand to tf32, costing ~2.8e-4 rms).
#define NW1_4 (768 * 256 / 4)
#define NW2_4 (256 * 256 / 4)
__global__ void round_w_tf32(const float* __restrict__ w1,
                             const float* __restrict__ w2,
                             float* __restrict__ w1o,
                             float* __restrict__ w2o)
{
    int i = blockIdx.x * blockDim.x + threadIdx.x;
    const float4* in; float4* out; int idx;
    if (i < NW1_4)              { in = (const float4*)w1; out = (float4*)w1o; idx = i; }
    else if (i < NW1_4 + NW2_4) { in = (const float4*)w2; out = (float4*)w2o; idx = i - NW1_4; }
    else return;
    float4 v = in[idx];
    out[idx] = make_float4(tf32r(v.x), tf32r(v.y), tf32r(v.z), tf32r(v.w));
}

__device__ __forceinline__ void mma_tf32(float c[4], const unsigned a[4], const unsigned b[2]) {
    asm volatile(
        "mma.sync.aligned.m16n8k8.row.col.f32.tf32.tf32.f32 "
        "{%0,%1,%2,%3}, {%4,%5,%6,%7}, {%8,%9}, {%0,%1,%2,%3};\n"
        : "+f"(c[0]), "+f"(c[1]), "+f"(c[2]), "+f"(c[3])
        : "r"(a[0]), "r"(a[1]), "r"(a[2]), "r"(a[3]), "r"(b[0]), "r"(b[1]));
}

__device__ __forceinline__ void ldsm_x4(unsigned r[4], const float* p) {
    unsigned addr = (unsigned)__cvta_generic_to_shared(p);
    asm volatile(
        "ldmatrix.sync.aligned.m8n8.x4.shared.b16 {%0,%1,%2,%3}, [%4];"
        : "=r"(r[0]), "=r"(r[1]), "=r"(r[2]), "=r"(r[3]) : "r"(addr));
}

__device__ __forceinline__ void cp_async16(void* smem, const void* gmem) {
    unsigned s = (unsigned)__cvta_generic_to_shared(smem);
    asm volatile("cp.async.cg.shared.global [%0], [%1], 16;" :: "r"(s), "l"(gmem));
}
#define CP_COMMIT() asm volatile("cp.async.commit_group;")
#define CP_WAIT0()  asm volatile("cp.async.wait_group 0;" ::: "memory")
#define CP_WAIT1()  asm volatile("cp.async.wait_group 1;" ::: "memory")

// ---------------------------------------------------------------------------
// TF32 tensor-core GEMM with bias, 3-stage cp.async pipeline (R11/R14 winner).
// Block 128x128x32, 8 warps, warp tile 64x32 (4x4 m16n8k8 frags).
// A staged [m][k] PADK=36 (ldmatrix conflict-free); B staged [k][n] PADN=136.
// ---------------------------------------------------------------------------
#define BK   32
#define PADK 36
#define PADN 136
#define AS_STAGE (128 * PADK)
#define BS_STAGE (BK * PADN)
#define SMEM_FLOATS (3 * AS_STAGE + 3 * BS_STAGE)
#define SMEM_BYTES  (SMEM_FLOATS * 4)

__global__ void __launch_bounds__(256, 2) gemm_tf32_bias(
    const float* __restrict__ W, const float* __restrict__ X,
    const float* __restrict__ bias, float* __restrict__ C,
    int M, int N, int K)
{
    extern __shared__ float smem[];
    float* const Abase = smem;
    float* const Bbase = smem + 3 * AS_STAGE;

    const int b  = blockIdx.z;
    const float* Xb = X + (size_t)b * K * N;
    float*       Cb = C + (size_t)b * M * N;
    const int m0 = blockIdx.y * 128;
    const int n0 = blockIdx.x * 128;
    const int tid  = threadIdx.x;
    const int lane = tid & 31;
    const int warp = tid >> 5;
    const int wm = (warp >> 2) * 64;
    const int wn = (warp & 3) * 32;
    const int g  = lane >> 2;
    const int t  = lane & 3;

    const int row_a = lane & 15;
    const int col_a = (lane >> 4) * 4;

    const int ar = tid & 127;
    const int akb = (tid >> 7) * 16;
    const int br = tid >> 5;
    const int bc = (tid & 31) * 4;

    const float* gA = &W[(size_t)(m0 + ar) * K + akb];
    const float* gB = &Xb[(size_t)br * N + n0 + bc];

    float acc[4][4][4];
#pragma unroll
    for (int i = 0; i < 4; ++i)
#pragma unroll
        for (int j = 0; j < 4; ++j)
#pragma unroll
            for (int r = 0; r < 4; ++r) acc[i][j][r] = 0.f;

    // Prologue: stages 0 and 1 in flight
#pragma unroll
    for (int st = 0; st < 2; ++st) {
        float* sA = Abase + st * AS_STAGE + ar * PADK + akb;
        float* sB = Bbase + st * BS_STAGE + br * PADN + bc;
        const int ko = st * BK;
#pragma unroll
        for (int i = 0; i < 4; ++i)
            cp_async16(sA + i * 4, gA + ko + i * 4);
#pragma unroll
        for (int j = 0; j < 4; ++j)
            cp_async16(sB + j * 8 * PADN, gB + (size_t)(ko + j * 8) * N);
        CP_COMMIT();
    }
    CP_WAIT1();
    __syncthreads();

    int cur = 0;
    for (int k0 = 0; k0 < K; k0 += BK) {
        const float* As = Abase + cur * AS_STAGE;
        const float* Bs = Bbase + cur * BS_STAGE;
#pragma unroll
        for (int kk = 0; kk < BK; kk += 8) {
            unsigned af[4][4], bf[4][2];
#pragma unroll
            for (int mt = 0; mt < 4; ++mt)
                ldsm_x4(af[mt], As + (wm + mt * 16 + row_a) * PADK + kk + col_a);
#pragma unroll
            for (int nt = 0; nt < 4; ++nt) {
                const int nb = wn + nt * 8;
                bf[nt][0] = __float_as_uint(Bs[(kk + t    ) * PADN + nb + g]);
                bf[nt][1] = __float_as_uint(Bs[(kk + t + 4) * PADN + nb + g]);
            }
#pragma unroll
            for (int mt = 0; mt < 4; ++mt)
#pragma unroll
                for (int nt = 0; nt < 4; ++nt)
                    mma_tf32(acc[mt][nt], af[mt], bf[nt]);
        }

        if (k0 + BK < K) {
            const int k2 = k0 + 2 * BK;
            if (k2 < K) {
                const int st = (cur + 2) % 3;
                float* sA = Abase + st * AS_STAGE + ar * PADK + akb;
                float* sB = Bbase + st * BS_STAGE + br * PADN + bc;
#pragma unroll
                for (int i = 0; i < 4; ++i)
                    cp_async16(sA + i * 4, gA + k2 + i * 4);
#pragma unroll
                for (int j = 0; j < 4; ++j)
                    cp_async16(sB + j * 8 * PADN, gB + (size_t)(k2 + j * 8) * N);
                CP_COMMIT();
                CP_WAIT1();
            } else {
                CP_WAIT0();
            }
            __syncthreads();
            cur = (cur + 1) % 3;
        }
    }

    // Epilogue: c0,c1 = row g, cols 2t,2t+1; c2,c3 = row g+8
#pragma unroll
    for (int mt = 0; mt < 4; ++mt) {
#pragma unroll
        for (int rh = 0; rh < 2; ++rh) {
            const int m = m0 + wm + mt * 16 + g + rh * 8;
            const float bv = bias[m];
#pragma unroll
            for (int nt = 0; nt < 4; ++nt) {
                float2 o;
                o.x = acc[mt][nt][rh * 2 + 0] + bv;
                o.y = acc[mt][nt][rh * 2 + 1] + bv;
                *(float2*)&Cb[(size_t)m * N + n0 + wn + nt * 8 + t * 2] = o;
            }
        }
    }
}

// ---------------------------------------------------------------------------
// Fused multi-range neighborhood attention (R14 winner logic), 128-thr blocks
// (finer scheduling quanta) + heavy-first head ordering.
// ---------------------------------------------------------------------------
template<int KS, int DIL>
__device__ __forceinline__ void attend_range(
    const float* __restrict__ qb, const float* __restrict__ kb,
    const float* __restrict__ vb, const float* __restrict__ s_erpb,
    float* __restrict__ ob, int x, int y)
{
    const int idx = y * WIDTH + x;

    float q[32];
#pragma unroll
    for (int d = 0; d < 32; ++d)
        q[d] = qb[(size_t)d * HW + idx] * 0.17677669529663687f;  // 32^-0.5

    float s = 0.f;
    float acc[32];
#pragma unroll
    for (int d = 0; d < 32; ++d) acc[d] = 0.f;

#pragma unroll 1
    for (int i = 0; i < KS; ++i) {
        const int ny = y + (i - KS / 2) * DIL;
        const bool iby = ((unsigned)ny < (unsigned)WIDTH);
#pragma unroll 1
        for (int j = 0; j < KS; ++j) {
            const int nx = x + (j - KS / 2) * DIL;
            const float erpb = s_erpb[i * KS + j];
            if (iby && ((unsigned)nx < (unsigned)WIDTH)) {
                const int nidx = ny * WIDTH + nx;
                float dot = 0.f;
#pragma unroll
                for (int d = 0; d < 32; ++d)
                    dot += q[d] * kb[(size_t)d * HW + nidx];
                const float p = __expf(dot) * erpb;
                s += p;
#pragma unroll
                for (int d = 0; d < 32; ++d)
                    acc[d] += p * vb[(size_t)d * HW + nidx];
            } else {
                s += erpb;   // OOB: logit = rpb, v = 0
            }
        }
    }

    const float inv = 1.f / s;
#pragma unroll
    for (int d = 0; d < 32; ++d)
        ob[(size_t)d * HW + idx] = tf32r(acc[d] * inv);
}

__global__ void __launch_bounds__(128, 4) attn_fused(
    const float* __restrict__ qkv,
    const float* __restrict__ rpb0, const float* __restrict__ rpb1,
    const float* __restrict__ rpb2, float* __restrict__ att)
{
    __shared__ float s_erpb[81];

    // Heavy-first head order: KS=9 (h=7), then KS=7 (h=4..6), then KS=5 (h=0..3).
    const int ord = blockIdx.z & 7;
    const int b   = blockIdx.z >> 3;
    static const __device__ int h_order[8] = {7, 4, 5, 6, 0, 1, 2, 3};
    const int h = h_order[ord];

    const int tid = threadIdx.y * 32 + threadIdx.x;

    if (h < 4) {
        if (tid < 25) s_erpb[tid] = __expf(rpb0[h * 25 + tid]);
    } else if (h < 7) {
        if (tid < 49) s_erpb[tid] = __expf(rpb1[(h - 4) * 49 + tid]);
    } else {
        if (tid < 81) s_erpb[tid] = __expf(rpb2[tid]);
    }
    __syncthreads();

    const int x = blockIdx.x * 32 + threadIdx.x;
    const int y = blockIdx.y * 4 + threadIdx.y;

    const float* qb = qkv + ((size_t)b * 768 + h * 32) * HW;
    const float* kb = qb + (size_t)256 * HW;
    const float* vb = qb + (size_t)512 * HW;
    float* ob = att + ((size_t)b * 256 + h * 32) * HW;

    if (h < 4)       attend_range<5, 1>(qb, kb, vb, s_erpb, ob, x, y);
    else if (h < 7)  attend_range<7, 2>(qb, kb, vb, s_erpb, ob, x, y);
    else             attend_range<9, 3>(qb, kb, vb, s_erpb, ob, x, y);
}

// ---------------------------------------------------------------------------
extern "C" void kernel_launch(void* const* d_in, const int* in_sizes, int n_in,
                              void* d_out, int out_size)
{
    const float* x      = (const float*)d_in[0];
    const float* qkv_w  = (const float*)d_in[1];
    const float* qkv_b  = (const float*)d_in[2];
    const float* proj_w = (const float*)d_in[3];
    const float* proj_b = (const float*)d_in[4];
    const float* rpb0   = (const float*)d_in[5];
    const float* rpb1   = (const float*)d_in[6];
    const float* rpb2   = (const float*)d_in[7];
    float* out = (float*)d_out;

    float *qkv_ptr, *att_ptr, *wqkv_ptr, *wproj_ptr;
    cudaGetSymbolAddress((void**)&qkv_ptr,  g_qkv);
    cudaGetSymbolAddress((void**)&att_ptr,  g_att);
    cudaGetSymbolAddress((void**)&wqkv_ptr, g_wqkv);
    cudaGetSymbolAddress((void**)&wproj_ptr,g_wproj);

    static bool attr_set = false;
    if (!attr_set) {
        cudaFuncSetAttribute(gemm_tf32_bias,
                             cudaFuncAttributeMaxDynamicSharedMemorySize, SMEM_BYTES);
        attr_set = true;
    }

    // 0) Pre-round only the weights to tf32 (x is truncated by MMA hardware)
    {
        const int total = NW1_4 + NW2_4;
        round_w_tf32<<<(total + 255) / 256, 256>>>(qkv_w, proj_w, wqkv_ptr, wproj_ptr);
    }

    // 1) QKV projection — TF32 tensor cores, 3-stage pipeline; B = raw x
    gemm_tf32_bias<<<dim3(32, 6, BATCH), 256, SMEM_BYTES>>>(wqkv_ptr, x, qkv_b, qkv_ptr, 768, HW, 256);

    // 2) Fused multi-range neighborhood attention, heavy-first, 128-thr blocks
    attn_fused<<<dim3(2, 16, BATCH * 8), dim3(32, 4)>>>(qkv_ptr, rpb0, rpb1, rpb2, att_ptr);

    // 3) Output projection — TF32 tensor cores, 3-stage pipeline
    gemm_tf32_bias<<<dim3(32, 2, BATCH), 256, SMEM_BYTES>>>(wproj_ptr, att_ptr, proj_b, out, 256, HW, 256);
}